// round 16
// baseline (speedup 1.0000x reference)
#include <cuda_runtime.h>
#include <cuda_fp16.h>
#include <cstdint>

// ---------------- problem constants ----------------
#define BB 4096
#define VV 20
#define DD 768
#define MROWS (BB * VV)        // 81920
#define NN (2 * DD)            // 1536 interleaved (m1,m2)
#define KK DD                  // 768
#define NEB (DD / 64)          // 12 e-blocks of 64

#define X_SCALE 64.0f
#define W_SCALE 16.0f
#define INV_SCALE (1.0f / (X_SCALE * W_SCALE))   // 2^-10 exact

// ---------------- scratch (static device globals; no allocations) ----------------
__device__ __half g_Xn[(size_t)MROWS * DD];   // softmax*64, fp16 (126 MB)
__device__ __half g_Wc[(size_t)NN * DD];      // interleaved weights*16, fp16 (2.4 MB)
__device__ __align__(16) float g_Halo[(size_t)MROWS * (NEB * 8)]; // fused halo cols (31.5 MB)

// ---------------- baseline-PTX helpers ----------------
__device__ __forceinline__ uint32_t smem_u32(const void* p) {
    uint32_t a;
    asm("{ .reg .u64 t; cvta.to.shared.u64 t, %1; cvt.u32.u64 %0, t; }" : "=r"(a) : "l"(p));
    return a;
}
__device__ __forceinline__ void cp_async16(uint32_t saddr, const void* gptr) {
    asm volatile("cp.async.cg.shared.global [%0], [%1], 16;\n" :: "r"(saddr), "l"(gptr));
}
#define CP_COMMIT() asm volatile("cp.async.commit_group;\n" ::: "memory")
#define CP_WAIT_1() asm volatile("cp.async.wait_group 1;\n" ::: "memory")
#define CP_WAIT_0() asm volatile("cp.async.wait_group 0;\n" ::: "memory")

__device__ __forceinline__ void ldsm_x4(uint32_t& r0, uint32_t& r1, uint32_t& r2, uint32_t& r3,
                                        uint32_t addr) {
    asm volatile("ldmatrix.sync.aligned.m8n8.x4.shared.b16 {%0,%1,%2,%3}, [%4];"
                 : "=r"(r0), "=r"(r1), "=r"(r2), "=r"(r3) : "r"(addr));
}
// fp16-accumulate HMMA: d,c are 2x .f16x2 regs — 2x rate vs f32-acc on HMMA pipes
__device__ __forceinline__ void mma16816_f16(uint32_t* d, const uint32_t* a, const uint32_t* b) {
    asm volatile(
        "mma.sync.aligned.m16n8k16.row.col.f16.f16.f16.f16 "
        "{%0,%1}, {%2,%3,%4,%5}, {%6,%7}, {%0,%1};"
        : "+r"(d[0]), "+r"(d[1])
        : "r"(a[0]), "r"(a[1]), "r"(a[2]), "r"(a[3]), "r"(b[0]), "r"(b[1]));
}

// ---------------- kernel 1: interleave + cast + scale weights ----------------
__global__ void prep_w(const float* __restrict__ W1, const float* __restrict__ W2) {
    int idx = blockIdx.x * blockDim.x + threadIdx.x;
    if (idx >= NN * DD) return;
    int n = idx / DD, k = idx - n * DD;
    int e = n >> 1;
    float v = (n & 1) ? W2[e * DD + k] : W1[e * DD + k];
    g_Wc[idx] = __float2half_rn(v * W_SCALE);
}

// ---------------- kernel 2: warp-per-row softmax -> fp16 * 64 ----------------
__global__ void __launch_bounds__(256) softmax_rows(const float* __restrict__ vf) {
    int wid = threadIdx.x >> 5, lane = threadIdx.x & 31;
    int row = blockIdx.x * 8 + wid;
    const float4* x4 = (const float4*)(vf + (size_t)row * DD);   // 192 float4/row
    float v[24];
    #pragma unroll
    for (int j = 0; j < 6; j++) {
        float4 f = x4[lane + 32 * j];
        v[4 * j] = f.x; v[4 * j + 1] = f.y; v[4 * j + 2] = f.z; v[4 * j + 3] = f.w;
    }
    float m = v[0];
    #pragma unroll
    for (int i = 1; i < 24; i++) m = fmaxf(m, v[i]);
    #pragma unroll
    for (int o = 16; o; o >>= 1) m = fmaxf(m, __shfl_xor_sync(0xffffffffu, m, o));
    float s = 0.f;
    #pragma unroll
    for (int i = 0; i < 24; i++) { v[i] = __expf(v[i] - m); s += v[i]; }
    #pragma unroll
    for (int o = 16; o; o >>= 1) s += __shfl_xor_sync(0xffffffffu, s, o);
    float inv = X_SCALE / s;

    uint2* dst = (uint2*)(g_Xn + (size_t)row * DD);   // 192 uint2/row
    #pragma unroll
    for (int j = 0; j < 6; j++) {
        __half2 lo = __floats2half2_rn(v[4 * j] * inv,     v[4 * j + 1] * inv);
        __half2 hi = __floats2half2_rn(v[4 * j + 2] * inv, v[4 * j + 3] * inv);
        uint2 pk;
        pk.x = *(uint32_t*)&lo;
        pk.y = *(uint32_t*)&hi;
        dst[lane + 32 * j] = pk;
    }
}

// ---------------- kernel 3: fp16-acc HMMA GEMM + fused bias/relu/conv epilogue ----------
#define TM 128
#define TN 128
#define KC 64
#define NKC (KK / KC)                      // 12
#define A_BYTES (TM * 128)
#define B_BYTES (TN * 128)
#define STAGE_BYTES (A_BYTES + B_BYTES)    // 32768
#define SM_TOTAL (2 * STAGE_BYTES)         // 65536
#define SF_STRIDE 64
#define SC_STRIDE 63

__device__ __forceinline__ uint32_t sw128(uint32_t off) {
    return off ^ ((off >> 3) & 0x70);
}

__device__ __forceinline__ void load_stage(uint32_t sbase, int s, int kc, int tid,
                                           const __half* Ab, const __half* Bw) {
    uint32_t abase = sbase + s * STAGE_BYTES;
    uint32_t bbase = abase + A_BYTES;
    #pragma unroll
    for (int t = 0; t < 4; t++) {
        int idx = tid + t * 256;
        int r = idx >> 3, i = idx & 7;
        uint32_t off = (uint32_t)(r * 128 + i * 16);
        cp_async16(abase + sw128(off), (const char*)(Ab + (size_t)r * DD + kc * KC) + i * 16);
    }
    #pragma unroll
    for (int t = 0; t < 4; t++) {
        int idx = tid + t * 256;
        int r = idx >> 3, i = idx & 7;
        uint32_t off = (uint32_t)(r * 128 + i * 16);
        cp_async16(bbase + sw128(off), (const char*)(Bw + (size_t)r * DD + kc * KC) + i * 16);
    }
    CP_COMMIT();
}

__global__ void __launch_bounds__(256) gemm_fused_kernel(const float* __restrict__ text,
                                                         const float* __restrict__ b1,
                                                         const float* __restrict__ b2,
                                                         const float* __restrict__ cw1,
                                                         const float* __restrict__ cb1,
                                                         const float* __restrict__ cw2,
                                                         const float* __restrict__ cb2,
                                                         float* __restrict__ out) {
    extern __shared__ char smem[];
    uint32_t sbase = smem_u32(smem);
    int tid = threadIdx.x, wid = tid >> 5, lane = tid & 31;
    int mw = wid & 3, nw = wid >> 2;           // warp grid 4(m) x 2(n), warp tile 32x64
    int eb = blockIdx.x;
    int n0 = eb * TN;
    int m0 = blockIdx.y * TM;

    const __half* Ab = g_Xn + (size_t)m0 * DD;
    const __half* Bw = g_Wc + (size_t)n0 * DD;

    float acc[2][8][4];                        // fp32 master accumulators
    #pragma unroll
    for (int i = 0; i < 2; i++)
        #pragma unroll
        for (int j = 0; j < 8; j++)
            #pragma unroll
            for (int q = 0; q < 4; q++) acc[i][j][q] = 0.f;

    load_stage(sbase, 0, 0, tid, Ab, Bw);

    for (int c = 0; c < NKC; c++) {
        int s = c & 1;
        if (c + 1 < NKC) {
            load_stage(sbase, s ^ 1, c + 1, tid, Ab, Bw);
            CP_WAIT_1();
        } else {
            CP_WAIT_0();
        }
        __syncthreads();

        uint32_t hacc[2][8][2];                // fp16 chunk accumulators (zeroed per chunk)
        #pragma unroll
        for (int i = 0; i < 2; i++)
            #pragma unroll
            for (int j = 0; j < 8; j++) { hacc[i][j][0] = 0u; hacc[i][j][1] = 0u; }

        uint32_t abase = sbase + s * STAGE_BYTES;
        uint32_t bbase = abase + A_BYTES;
        #pragma unroll
        for (int ks = 0; ks < 4; ks++) {
            uint32_t a[2][4];
            #pragma unroll
            for (int mf = 0; mf < 2; mf++) {
                int row = mw * 32 + mf * 16 + (lane & 15);
                uint32_t off = (uint32_t)(row * 128 + ((lane >> 4) * 16) + ks * 32);
                ldsm_x4(a[mf][0], a[mf][1], a[mf][2], a[mf][3], abase + sw128(off));
            }
            uint32_t b[8][2];
            #pragma unroll
            for (int nf2 = 0; nf2 < 4; nf2++) {
                int nrow = nw * 64 + nf2 * 16 + (lane & 7) + (((lane >> 4) & 1) << 3);
                uint32_t off = (uint32_t)(nrow * 128 + (((lane >> 3) & 1) * 16) + ks * 32);
                uint32_t r0, r1, r2, r3;
                ldsm_x4(r0, r1, r2, r3, bbase + sw128(off));
                b[nf2 * 2][0] = r0;     b[nf2 * 2][1] = r1;
                b[nf2 * 2 + 1][0] = r2; b[nf2 * 2 + 1][1] = r3;
            }
            #pragma unroll
            for (int mf = 0; mf < 2; mf++)
                #pragma unroll
                for (int nf = 0; nf < 8; nf++)
                    mma16816_f16(hacc[mf][nf], a[mf], b[nf]);
        }

        // split-K: fold fp16 chunk sums into fp32 masters
        #pragma unroll
        for (int mf = 0; mf < 2; mf++)
            #pragma unroll
            for (int nf = 0; nf < 8; nf++) {
                float2 f0 = __half22float2(*(__half2*)&hacc[mf][nf][0]);
                float2 f1 = __half22float2(*(__half2*)&hacc[mf][nf][1]);
                acc[mf][nf][0] += f0.x;
                acc[mf][nf][1] += f0.y;
                acc[mf][nf][2] += f1.x;
                acc[mf][nf][3] += f1.y;
            }
        __syncthreads();
    }

    // ---- phase 1: fused = relu(text*(m1+b1) + (m2+b2)) -> SF; export 8 halo cols ----
    float* SF = (float*)smem;                  // [128][SF_STRIDE]
    float* SC = SF + 128 * SF_STRIDE;          // [128][SC_STRIDE]
    #pragma unroll
    for (int mf = 0; mf < 2; mf++) {
        int ml_a = mw * 32 + mf * 16 + (lane >> 2);
        int ml_b = ml_a + 8;
        int m_a = m0 + ml_a, m_b = m0 + ml_b;
        const float* trow_a = text + (size_t)(m_a / VV) * DD;
        const float* trow_b = text + (size_t)(m_b / VV) * DD;
        #pragma unroll
        for (int nf = 0; nf < 8; nf++) {
            int e_l = nw * 32 + nf * 4 + (lane & 3);
            int e_g = eb * 64 + e_l;
            float bb1 = __ldg(b1 + e_g), bb2 = __ldg(b2 + e_g);
            float va = fmaxf(fmaf(__ldg(trow_a + e_g),
                                  fmaf(acc[mf][nf][0], INV_SCALE, bb1),
                                  fmaf(acc[mf][nf][1], INV_SCALE, bb2)), 0.f);
            float vb = fmaxf(fmaf(__ldg(trow_b + e_g),
                                  fmaf(acc[mf][nf][2], INV_SCALE, bb1),
                                  fmaf(acc[mf][nf][3], INV_SCALE, bb2)), 0.f);
            SF[ml_a * SF_STRIDE + e_l] = va;
            SF[ml_b * SF_STRIDE + e_l] = vb;
            if (e_l < 4 || e_l >= 60) {
                int sl = (e_l < 4) ? e_l : (e_l - 56);
                g_Halo[(size_t)m_a * (NEB * 8) + eb * 8 + sl] = va;
                g_Halo[(size_t)m_b * (NEB * 8) + eb * 8 + sl] = vb;
            }
        }
    }
    __syncthreads();

    // ---- phase 2: conv1 + relu for e_l in [1,63) -> SC[ml][e_l-1] ----
    float w10 = __ldg(cw1), w11 = __ldg(cw1 + 1), w12 = __ldg(cw1 + 2), bc1 = __ldg(cb1);
    #pragma unroll
    for (int t = 0; t < 32; t++) {
        int idx = tid + t * 256;
        int ml = idx >> 6, j = idx & 63;
        if (j < 62) {
            const float* F = SF + ml * SF_STRIDE + j;
            SC[ml * SC_STRIDE + j] = fmaxf(w10 * F[0] + w11 * F[1] + w12 * F[2] + bc1, 0.f);
        }
    }
    __syncthreads();

    // ---- phase 3: conv2 for e_l in [2,62) -> out (60 interior cols) ----
    float w20 = __ldg(cw2), w21 = __ldg(cw2 + 1), w22 = __ldg(cw2 + 2), bc2 = __ldg(cb2);
    #pragma unroll
    for (int t = 0; t < 32; t++) {
        int idx = tid + t * 256;
        int ml = idx >> 6, i = idx & 63;
        if (i < 60) {
            const float* C = SC + ml * SC_STRIDE + i;
            out[(size_t)(m0 + ml) * DD + eb * 64 + i + 2] =
                w20 * C[0] + w21 * C[1] + w22 * C[2] + bc2;
        }
    }
}

// ---------------- kernel 4: boundary fixup (R12 exact: thread per column) ----------------
__device__ __forceinline__ float halo_F(const float* __restrict__ H, int x) {
    if (x < 0 || x >= DD) return 0.f;
    int ebx = x >> 6, off = x & 63;
    int sl = (off < 4) ? off : (off - 56);
    return H[ebx * 8 + sl];
}

__global__ void __launch_bounds__(256) fixup_kernel(const float* __restrict__ cw1,
                                                    const float* __restrict__ cb1,
                                                    const float* __restrict__ cw2,
                                                    const float* __restrict__ cb2,
                                                    float* __restrict__ out) {
    int idx = blockIdx.x * 256 + threadIdx.x;
    if (idx >= MROWS * 48) return;
    int m = idx / 48, q = idx - m * 48;
    int eb = q >> 2, t = q & 3;
    int e_l = (t < 2) ? t : (t + 60);                 // {0,1,62,63}
    int e = eb * 64 + e_l;
    const float* H = g_Halo + (size_t)m * (NEB * 8);
    float w10 = __ldg(cw1), w11 = __ldg(cw1 + 1), w12 = __ldg(cw1 + 2), bc1 = __ldg(cb1);
    float w20 = __ldg(cw2), w21 = __ldg(cw2 + 1), w22 = __ldg(cw2 + 2), bc2 = __ldg(cb2);
    float F[5];
    #pragma unroll
    for (int d = 0; d < 5; d++) F[d] = halo_F(H, e - 2 + d);
    float c1m = (e - 1 < 0)    ? 0.f : fmaxf(w10 * F[0] + w11 * F[1] + w12 * F[2] + bc1, 0.f);
    float c1c =                        fmaxf(w10 * F[1] + w11 * F[2] + w12 * F[3] + bc1, 0.f);
    float c1p = (e + 1 >= DD)  ? 0.f : fmaxf(w10 * F[2] + w11 * F[3] + w12 * F[4] + bc1, 0.f);
    out[(size_t)m * DD + e] = w20 * c1m + w21 * c1c + w22 * c1p + bc2;
}

// ---------------- launch (single stream) ----------------
extern "C" void kernel_launch(void* const* d_in, const int* in_sizes, int n_in,
                              void* d_out, int out_size) {
    const float* text = (const float*)d_in[0];
    const float* vf   = (const float*)d_in[1];
    const float* W1   = (const float*)d_in[2];
    const float* b1   = (const float*)d_in[3];
    const float* W2   = (const float*)d_in[4];
    const float* b2   = (const float*)d_in[5];
    const float* cw1  = (const float*)d_in[6];
    const float* cb1  = (const float*)d_in[7];
    const float* cw2  = (const float*)d_in[8];
    const float* cb2  = (const float*)d_in[9];
    float* out = (float*)d_out;

    cudaFuncSetAttribute(gemm_fused_kernel, cudaFuncAttributeMaxDynamicSharedMemorySize, SM_TOTAL);

    prep_w<<<(NN * DD + 255) / 256, 256>>>(W1, W2);
    softmax_rows<<<MROWS / 8, 256>>>(vf);
    gemm_fused_kernel<<<dim3(NEB, MROWS / TM), 256, SM_TOTAL>>>(
        text, b1, b2, cw1, cb1, cw2, cb2, out);
    fixup_kernel<<<(MROWS * 48 + 255) / 256, 256>>>(cw1, cb1, cw2, cb2, out);
}

// round 17
// speedup vs baseline: 1.4551x; 1.4551x over previous
#include <cuda_runtime.h>
#include <cuda_bf16.h>
#include <cstdint>

// ---------------- problem constants ----------------
#define BB 4096
#define VV 20
#define DD 768
#define MROWS (BB * VV)        // 81920
#define NN (2 * DD)            // 1536 interleaved (m1,m2)
#define KK DD                  // 768
#define NEB (DD / 64)          // 12 e-blocks of 64

// ---------------- scratch (static device globals; no allocations) ----------------
__device__ __nv_bfloat16 g_Xn[(size_t)MROWS * DD];   // softmaxed A, bf16 (126 MB)
__device__ __nv_bfloat16 g_Wc[(size_t)NN * DD];      // interleaved weights bf16 (2.4 MB)
__device__ __align__(16) float g_Halo[(size_t)MROWS * (NEB * 8)]; // fused halo cols (31.5 MB)

// ---------------- baseline-PTX helpers ----------------
__device__ __forceinline__ uint32_t smem_u32(const void* p) {
    uint32_t a;
    asm("{ .reg .u64 t; cvta.to.shared.u64 t, %1; cvt.u32.u64 %0, t; }" : "=r"(a) : "l"(p));
    return a;
}
__device__ __forceinline__ void cp_async16(uint32_t saddr, const void* gptr) {
    asm volatile("cp.async.cg.shared.global [%0], [%1], 16;\n" :: "r"(saddr), "l"(gptr));
}
#define CP_COMMIT() asm volatile("cp.async.commit_group;\n" ::: "memory")
#define CP_WAIT_1() asm volatile("cp.async.wait_group 1;\n" ::: "memory")
#define CP_WAIT_0() asm volatile("cp.async.wait_group 0;\n" ::: "memory")

__device__ __forceinline__ void ldsm_x4(uint32_t& r0, uint32_t& r1, uint32_t& r2, uint32_t& r3,
                                        uint32_t addr) {
    asm volatile("ldmatrix.sync.aligned.m8n8.x4.shared.b16 {%0,%1,%2,%3}, [%4];"
                 : "=r"(r0), "=r"(r1), "=r"(r2), "=r"(r3) : "r"(addr));
}
__device__ __forceinline__ void mma16816(float* c, const uint32_t* a, const uint32_t* b) {
    asm volatile(
        "mma.sync.aligned.m16n8k16.row.col.f32.bf16.bf16.f32 "
        "{%0,%1,%2,%3}, {%4,%5,%6,%7}, {%8,%9}, {%0,%1,%2,%3};"
        : "+f"(c[0]), "+f"(c[1]), "+f"(c[2]), "+f"(c[3])
        : "r"(a[0]), "r"(a[1]), "r"(a[2]), "r"(a[3]), "r"(b[0]), "r"(b[1]));
}

// ---------------- kernel 1: interleave + cast weights ----------------
__global__ void prep_w(const float* __restrict__ W1, const float* __restrict__ W2) {
    int idx = blockIdx.x * blockDim.x + threadIdx.x;
    if (idx >= NN * DD) return;
    int n = idx / DD, k = idx - n * DD;
    int e = n >> 1;
    float v = (n & 1) ? W2[e * DD + k] : W1[e * DD + k];
    g_Wc[idx] = __float2bfloat16(v);
}

// ---------------- kernel 2: warp-per-row softmax -> bf16 (direct coalesced stores) -------
__global__ void __launch_bounds__(256) softmax_rows(const float* __restrict__ vf) {
    int wid = threadIdx.x >> 5, lane = threadIdx.x & 31;
    int row = blockIdx.x * 8 + wid;
    const float4* x4 = (const float4*)(vf + (size_t)row * DD);   // 192 float4/row
    float v[24];
    #pragma unroll
    for (int j = 0; j < 6; j++) {
        float4 f = x4[lane + 32 * j];
        v[4 * j] = f.x; v[4 * j + 1] = f.y; v[4 * j + 2] = f.z; v[4 * j + 3] = f.w;
    }
    float m = v[0];
    #pragma unroll
    for (int i = 1; i < 24; i++) m = fmaxf(m, v[i]);
    #pragma unroll
    for (int o = 16; o; o >>= 1) m = fmaxf(m, __shfl_xor_sync(0xffffffffu, m, o));
    float s = 0.f;
    #pragma unroll
    for (int i = 0; i < 24; i++) { v[i] = __expf(v[i] - m); s += v[i]; }
    #pragma unroll
    for (int o = 16; o; o >>= 1) s += __shfl_xor_sync(0xffffffffu, s, o);
    float inv = 1.f / s;

    uint2* dst = (uint2*)(g_Xn + (size_t)row * DD);   // 192 uint2/row
    #pragma unroll
    for (int j = 0; j < 6; j++) {
        __nv_bfloat162 lo = __floats2bfloat162_rn(v[4 * j] * inv,     v[4 * j + 1] * inv);
        __nv_bfloat162 hi = __floats2bfloat162_rn(v[4 * j + 2] * inv, v[4 * j + 3] * inv);
        uint2 pk;
        pk.x = *(uint32_t*)&lo;
        pk.y = *(uint32_t*)&hi;
        dst[lane + 32 * j] = pk;
    }
}

// ---------------- kernel 3: bf16 GEMM (occ2) + fused bias/relu/conv epilogue ----------
#define TM 128
#define TN 128
#define KC 64
#define NKC (KK / KC)                      // 12
#define A_BYTES (TM * 128)
#define B_BYTES (TN * 128)
#define STAGE_BYTES (A_BYTES + B_BYTES)    // 32768
#define SM_TOTAL (2 * STAGE_BYTES)         // 65536
#define SF_STRIDE 64
#define SC_STRIDE 63

__device__ __forceinline__ uint32_t sw128(uint32_t off) {
    return off ^ ((off >> 3) & 0x70);
}

__device__ __forceinline__ void load_stage(uint32_t sbase, int s, int kc, int tid,
                                           const __nv_bfloat16* Ab, const __nv_bfloat16* Bw) {
    uint32_t abase = sbase + s * STAGE_BYTES;
    uint32_t bbase = abase + A_BYTES;
    #pragma unroll
    for (int t = 0; t < 4; t++) {
        int idx = tid + t * 256;
        int r = idx >> 3, i = idx & 7;
        uint32_t off = (uint32_t)(r * 128 + i * 16);
        cp_async16(abase + sw128(off), (const char*)(Ab + (size_t)r * DD + kc * KC) + i * 16);
    }
    #pragma unroll
    for (int t = 0; t < 4; t++) {
        int idx = tid + t * 256;
        int r = idx >> 3, i = idx & 7;
        uint32_t off = (uint32_t)(r * 128 + i * 16);
        cp_async16(bbase + sw128(off), (const char*)(Bw + (size_t)r * DD + kc * KC) + i * 16);
    }
    CP_COMMIT();
}

__global__ void __launch_bounds__(256, 2) gemm_fused_kernel(const float* __restrict__ text,
                                                            const float* __restrict__ b1,
                                                            const float* __restrict__ b2,
                                                            const float* __restrict__ cw1,
                                                            const float* __restrict__ cb1,
                                                            const float* __restrict__ cw2,
                                                            const float* __restrict__ cb2,
                                                            float* __restrict__ out) {
    extern __shared__ char smem[];
    uint32_t sbase = smem_u32(smem);
    int tid = threadIdx.x, wid = tid >> 5, lane = tid & 31;
    int mw = wid & 3, nw = wid >> 2;           // warp grid 4(m) x 2(n), warp tile 32x64
    int eb = blockIdx.x;
    int n0 = eb * TN;
    int m0 = blockIdx.y * TM;

    const __nv_bfloat16* Ab = g_Xn + (size_t)m0 * DD;
    const __nv_bfloat16* Bw = g_Wc + (size_t)n0 * DD;

    float acc[2][8][4];
    #pragma unroll
    for (int i = 0; i < 2; i++)
        #pragma unroll
        for (int j = 0; j < 8; j++)
            #pragma unroll
            for (int q = 0; q < 4; q++) acc[i][j][q] = 0.f;

    load_stage(sbase, 0, 0, tid, Ab, Bw);

    for (int c = 0; c < NKC; c++) {
        int s = c & 1;
        if (c + 1 < NKC) {
            load_stage(sbase, s ^ 1, c + 1, tid, Ab, Bw);
            CP_WAIT_1();
        } else {
            CP_WAIT_0();
        }
        __syncthreads();

        uint32_t abase = sbase + s * STAGE_BYTES;
        uint32_t bbase = abase + A_BYTES;
        #pragma unroll
        for (int ks = 0; ks < 4; ks++) {
            uint32_t a[2][4];
            #pragma unroll
            for (int mf = 0; mf < 2; mf++) {
                int row = mw * 32 + mf * 16 + (lane & 15);
                uint32_t off = (uint32_t)(row * 128 + ((lane >> 4) * 16) + ks * 32);
                ldsm_x4(a[mf][0], a[mf][1], a[mf][2], a[mf][3], abase + sw128(off));
            }
            uint32_t b[8][2];
            #pragma unroll
            for (int nf2 = 0; nf2 < 4; nf2++) {
                int nrow = nw * 64 + nf2 * 16 + (lane & 7) + (((lane >> 4) & 1) << 3);
                uint32_t off = (uint32_t)(nrow * 128 + (((lane >> 3) & 1) * 16) + ks * 32);
                uint32_t r0, r1, r2, r3;
                ldsm_x4(r0, r1, r2, r3, bbase + sw128(off));
                b[nf2 * 2][0] = r0;     b[nf2 * 2][1] = r1;
                b[nf2 * 2 + 1][0] = r2; b[nf2 * 2 + 1][1] = r3;
            }
            #pragma unroll
            for (int mf = 0; mf < 2; mf++)
                #pragma unroll
                for (int nf = 0; nf < 8; nf++)
                    mma16816(acc[mf][nf], a[mf], b[nf]);
        }
        __syncthreads();
    }

    // ---- phase 1: fused = relu(text*(m1+b1) + (m2+b2)) -> SF; export 8 halo cols ----
    float* SF = (float*)smem;                  // [128][SF_STRIDE]
    float* SC = SF + 128 * SF_STRIDE;          // [128][SC_STRIDE]
    #pragma unroll
    for (int mf = 0; mf < 2; mf++) {
        int ml_a = mw * 32 + mf * 16 + (lane >> 2);
        int ml_b = ml_a + 8;
        int m_a = m0 + ml_a, m_b = m0 + ml_b;
        const float* trow_a = text + (size_t)(m_a / VV) * DD;
        const float* trow_b = text + (size_t)(m_b / VV) * DD;
        #pragma unroll
        for (int nf = 0; nf < 8; nf++) {
            int e_l = nw * 32 + nf * 4 + (lane & 3);
            int e_g = eb * 64 + e_l;
            float bb1 = __ldg(b1 + e_g), bb2 = __ldg(b2 + e_g);
            float va = fmaxf(fmaf(__ldg(trow_a + e_g), acc[mf][nf][0] + bb1,
                                  acc[mf][nf][1] + bb2), 0.f);
            float vb = fmaxf(fmaf(__ldg(trow_b + e_g), acc[mf][nf][2] + bb1,
                                  acc[mf][nf][3] + bb2), 0.f);
            SF[ml_a * SF_STRIDE + e_l] = va;
            SF[ml_b * SF_STRIDE + e_l] = vb;
            if (e_l < 4 || e_l >= 60) {
                int sl = (e_l < 4) ? e_l : (e_l - 56);
                g_Halo[(size_t)m_a * (NEB * 8) + eb * 8 + sl] = va;
                g_Halo[(size_t)m_b * (NEB * 8) + eb * 8 + sl] = vb;
            }
        }
    }
    __syncthreads();

    // ---- phase 2: conv1 + relu for e_l in [1,63) -> SC[ml][e_l-1] (pow2 indexing) ----
    float w10 = __ldg(cw1), w11 = __ldg(cw1 + 1), w12 = __ldg(cw1 + 2), bc1 = __ldg(cb1);
    #pragma unroll
    for (int t = 0; t < 32; t++) {
        int idx = tid + t * 256;               // 128*64 total
        int ml = idx >> 6, j = idx & 63;
        if (j < 62) {
            const float* F = SF + ml * SF_STRIDE + j;
            SC[ml * SC_STRIDE + j] = fmaxf(w10 * F[0] + w11 * F[1] + w12 * F[2] + bc1, 0.f);
        }
    }
    __syncthreads();

    // ---- phase 3: conv2 for e_l in [2,62) -> out (60 interior cols) ----
    float w20 = __ldg(cw2), w21 = __ldg(cw2 + 1), w22 = __ldg(cw2 + 2), bc2 = __ldg(cb2);
    #pragma unroll
    for (int t = 0; t < 32; t++) {
        int idx = tid + t * 256;
        int ml = idx >> 6, i = idx & 63;
        if (i < 60) {
            const float* C = SC + ml * SC_STRIDE + i;
            out[(size_t)(m0 + ml) * DD + eb * 64 + i + 2] =
                w20 * C[0] + w21 * C[1] + w22 * C[2] + bc2;
        }
    }
}

// ---------------- kernel 4: boundary fixup (R12 exact: thread per column) ----------------
__device__ __forceinline__ float halo_F(const float* __restrict__ H, int x) {
    if (x < 0 || x >= DD) return 0.f;
    int ebx = x >> 6, off = x & 63;
    int sl = (off < 4) ? off : (off - 56);
    return H[ebx * 8 + sl];
}

__global__ void __launch_bounds__(256) fixup_kernel(const float* __restrict__ cw1,
                                                    const float* __restrict__ cb1,
                                                    const float* __restrict__ cw2,
                                                    const float* __restrict__ cb2,
                                                    float* __restrict__ out) {
    int idx = blockIdx.x * 256 + threadIdx.x;
    if (idx >= MROWS * 48) return;
    int m = idx / 48, q = idx - m * 48;
    int eb = q >> 2, t = q & 3;
    int e_l = (t < 2) ? t : (t + 60);                 // {0,1,62,63}
    int e = eb * 64 + e_l;
    const float* H = g_Halo + (size_t)m * (NEB * 8);
    float w10 = __ldg(cw1), w11 = __ldg(cw1 + 1), w12 = __ldg(cw1 + 2), bc1 = __ldg(cb1);
    float w20 = __ldg(cw2), w21 = __ldg(cw2 + 1), w22 = __ldg(cw2 + 2), bc2 = __ldg(cb2);
    float F[5];
    #pragma unroll
    for (int d = 0; d < 5; d++) F[d] = halo_F(H, e - 2 + d);
    float c1m = (e - 1 < 0)    ? 0.f : fmaxf(w10 * F[0] + w11 * F[1] + w12 * F[2] + bc1, 0.f);
    float c1c =                        fmaxf(w10 * F[1] + w11 * F[2] + w12 * F[3] + bc1, 0.f);
    float c1p = (e + 1 >= DD)  ? 0.f : fmaxf(w10 * F[2] + w11 * F[3] + w12 * F[4] + bc1, 0.f);
    out[(size_t)m * DD + e] = w20 * c1m + w21 * c1c + w22 * c1p + bc2;
}

// ---------------- launch (single stream) ----------------
extern "C" void kernel_launch(void* const* d_in, const int* in_sizes, int n_in,
                              void* d_out, int out_size) {
    const float* text = (const float*)d_in[0];
    const float* vf   = (const float*)d_in[1];
    const float* W1   = (const float*)d_in[2];
    const float* b1   = (const float*)d_in[3];
    const float* W2   = (const float*)d_in[4];
    const float* b2   = (const float*)d_in[5];
    const float* cw1  = (const float*)d_in[6];
    const float* cb1  = (const float*)d_in[7];
    const float* cw2  = (const float*)d_in[8];
    const float* cb2  = (const float*)d_in[9];
    float* out = (float*)d_out;

    cudaFuncSetAttribute(gemm_fused_kernel, cudaFuncAttributeMaxDynamicSharedMemorySize, SM_TOTAL);

    prep_w<<<(NN * DD + 255) / 256, 256>>>(W1, W2);
    softmax_rows<<<MROWS / 8, 256>>>(vf);
    gemm_fused_kernel<<<dim3(NEB, MROWS / TM), 256, SM_TOTAL>>>(
        text, b1, b2, cw1, cb1, cw2, cb2, out);
    fixup_kernel<<<(MROWS * 48 + 255) / 256, 256>>>(cw1, cb1, cw2, cb2, out);
}